// round 3
// baseline (speedup 1.0000x reference)
#include <cuda_runtime.h>

// ---------------------------------------------------------------------------
// Quanvolution filter, algebraically collapsed:
//   <Z_w>(patch) = sum_{t in {I,C,S}^4} coef[w][t] * prod_i f_{t_i}(x_i)
// where f_I = 1, f_C = cos(x_i), f_S = sin(x_i).
// coef (4 x 81 floats) depends only on params -> computed once by setup kernel.
// ---------------------------------------------------------------------------

#define N_PATCHES (4096 * 196)

__device__ float g_coef[4 * 81];

struct cplx { float re, im; };
__device__ __forceinline__ cplx cmul(cplx a, cplx b) {
    return { a.re * b.re - a.im * b.im, a.re * b.im + a.im * b.re };
}
__device__ __forceinline__ cplx cadd(cplx a, cplx b) {
    return { a.re + b.re, a.im + b.im };
}

// One block, >=324 threads.
// Phase 1: threads 0..15 simulate circuit on basis state e_j -> column j of W.
// Phase 2: threads 0..255 compute A_w[j][k] = sum_m z_w(m) Re(conj(W[m,j]) W[m,k]).
// Phase 3: threads 0..323 expand A into the 324 multilinear coefficients.
__global__ void quanv_setup_kernel(const float* __restrict__ params)
{
    __shared__ float Wr[16][16];  // Wr[m][j]
    __shared__ float Wi[16][16];
    __shared__ float A[4][16][16];

    const int tid = threadIdx.x;

    if (tid < 16) {
        cplx s[16];
        #pragma unroll
        for (int m = 0; m < 16; m++) s[m] = { 0.f, 0.f };
        s[tid] = { 1.f, 0.f };

        for (int l = 0; l < 2; l++) {
            // single-qubit gates G = RX(p2) RZ(p1) RY(p0) on each wire
            for (int w = 0; w < 4; w++) {
                const float a = params[(l * 4 + w) * 3 + 0] * 0.5f;
                const float b = params[(l * 4 + w) * 3 + 1] * 0.5f;
                const float c = params[(l * 4 + w) * 3 + 2] * 0.5f;
                const float ca = cosf(a), sa = sinf(a);
                const float cb = cosf(b), sb = sinf(b);
                const float cc = cosf(c), sc = sinf(c);
                // RZ @ RY
                cplx m00 = {  cb * ca, -sb * ca };
                cplx m01 = { -cb * sa,  sb * sa };
                cplx m10 = {  cb * sa,  sb * sa };
                cplx m11 = {  cb * ca,  sb * ca };
                // RX @ (RZ @ RY)
                cplx rx00 = { cc, 0.f }, rx01 = { 0.f, -sc };
                cplx rx10 = { 0.f, -sc }, rx11 = { cc, 0.f };
                cplx G00 = cadd(cmul(rx00, m00), cmul(rx01, m10));
                cplx G01 = cadd(cmul(rx00, m01), cmul(rx01, m11));
                cplx G10 = cadd(cmul(rx10, m00), cmul(rx11, m10));
                cplx G11 = cadd(cmul(rx10, m01), cmul(rx11, m11));

                const int mask = 8 >> w;   // wire w bit is (3 - w)
                #pragma unroll
                for (int m = 0; m < 16; m++) {
                    if (m & mask) continue;
                    cplx s0 = s[m], s1 = s[m | mask];
                    s[m]        = cadd(cmul(G00, s0), cmul(G01, s1));
                    s[m | mask] = cadd(cmul(G10, s0), cmul(G11, s1));
                }
            }
            // CNOT ring: (0,1) (1,2) (2,3) (3,0)
            const int cw[4] = { 0, 1, 2, 3 };
            const int tw[4] = { 1, 2, 3, 0 };
            for (int q = 0; q < 4; q++) {
                const int mc = 8 >> cw[q];
                const int mt = 8 >> tw[q];
                #pragma unroll
                for (int m = 0; m < 16; m++) {
                    if ((m & mc) && !(m & mt)) {
                        cplx tmp = s[m]; s[m] = s[m | mt]; s[m | mt] = tmp;
                    }
                }
            }
        }
        #pragma unroll
        for (int m = 0; m < 16; m++) { Wr[m][tid] = s[m].re; Wi[m][tid] = s[m].im; }
    }
    __syncthreads();

    if (tid < 256) {
        const int j = tid >> 4, k = tid & 15;
        float acc0 = 0.f, acc1 = 0.f, acc2 = 0.f, acc3 = 0.f;
        #pragma unroll
        for (int m = 0; m < 16; m++) {
            const float v = Wr[m][j] * Wr[m][k] + Wi[m][j] * Wi[m][k];
            acc0 += ((m >> 3) & 1) ? -v : v;
            acc1 += ((m >> 2) & 1) ? -v : v;
            acc2 += ((m >> 1) & 1) ? -v : v;
            acc3 += ( m       & 1) ? -v : v;
        }
        A[0][j][k] = acc0; A[1][j][k] = acc1; A[2][j][k] = acc2; A[3][j][k] = acc3;
    }
    __syncthreads();

    if (tid < 324) {
        const int w = tid / 81, q = tid % 81;
        const int t0 = q / 27, t1 = (q / 9) % 3, t2 = (q / 3) % 3, t3 = q % 3;
        const int t[4] = { t0, t1, t2, t3 };
        float c = 0.f;
        for (int j = 0; j < 16; j++) {
            for (int k = 0; k < 16; k++) {
                float h = 1.f;
                #pragma unroll
                for (int i = 0; i < 4; i++) {
                    const int jb = (j >> (3 - i)) & 1;
                    const int kb = (k >> (3 - i)) & 1;
                    const int ti = t[i];
                    float hv;
                    if (ti == 2)       hv = (jb != kb) ? 0.5f : 0.f;        // sin x
                    else if (jb != kb) hv = 0.f;
                    else if (ti == 1)  hv = jb ? -0.5f : 0.5f;              // cos x
                    else               hv = 0.5f;                           // 1
                    h *= hv;
                }
                c = fmaf(A[w][j][k], h, c);
            }
        }
        g_coef[tid] = c;
    }
}

// ---------------------------------------------------------------------------
// Main kernel: one wire per thread (w = tid & 3, loop-invariant), 81 coefs in
// registers, grid-stride over patches. 80 FFMA + 4 __sincosf per task.
// ---------------------------------------------------------------------------
__global__ void __launch_bounds__(128)
quanv_main_kernel(const float* __restrict__ x, float* __restrict__ out)
{
    const int tid = blockIdx.x * blockDim.x + threadIdx.x;
    const int w = tid & 3;

    float cf[81];
    const float* cw = g_coef + w * 81;
    #pragma unroll
    for (int i = 0; i < 81; i++) cf[i] = cw[i];

    const int pstride = (gridDim.x * blockDim.x) >> 2;

    for (int pidx = tid >> 2; pidx < N_PATCHES; pidx += pstride) {
        const int b   = pidx / 196;
        const int p   = pidx - b * 196;
        const int r   = p / 14;
        const int col = p - r * 14;

        const float* xp = x + b * 784 + r * 56 + col * 2;
        const float x0 = xp[0];
        const float x1 = xp[1];
        const float x2 = xp[28];
        const float x3 = xp[29];

        float s0, c0, s1, c1, s2, c2, s3, c3;
        __sincosf(x0, &s0, &c0);
        __sincosf(x1, &s1, &c1);
        __sincosf(x2, &s2, &c2);
        __sincosf(x3, &s3, &c3);

        float r3[27];
        #pragma unroll
        for (int t = 0; t < 27; t++)
            r3[t] = fmaf(cf[3 * t + 2], s3, fmaf(cf[3 * t + 1], c3, cf[3 * t]));
        float r2[9];
        #pragma unroll
        for (int t = 0; t < 9; t++)
            r2[t] = fmaf(r3[3 * t + 2], s2, fmaf(r3[3 * t + 1], c2, r3[3 * t]));
        float r1[3];
        #pragma unroll
        for (int t = 0; t < 3; t++)
            r1[t] = fmaf(r2[3 * t + 2], s1, fmaf(r2[3 * t + 1], c1, r2[3 * t]));
        const float res = fmaf(r1[2], s0, fmaf(r1[1], c0, r1[0]));

        out[pidx * 4 + w] = res;
    }
}

extern "C" void kernel_launch(void* const* d_in, const int* in_sizes, int n_in,
                              void* d_out, int out_size)
{
    // metadata order: x (4096*28*28), params (2*4*3). Guard by size anyway.
    const float* x      = (const float*)d_in[0];
    const float* params = (const float*)d_in[1];
    if (n_in >= 2 && in_sizes[0] == 24) {
        params = (const float*)d_in[0];
        x      = (const float*)d_in[1];
    }
    float* out = (float*)d_out;

    quanv_setup_kernel<<<1, 384>>>(params);
    quanv_main_kernel<<<1184, 128>>>(x, out);
}

// round 4
// speedup vs baseline: 1.3010x; 1.3010x over previous
#include <cuda_runtime.h>

// ---------------------------------------------------------------------------
// Quanvolution filter, algebraically collapsed:
//   <Z_w>(patch) = sum_{t in {I,C,S}^4} coef[w][t] * prod_i f_{t_i}(x_i)
// f_I = 1, f_C = cos(x_i), f_S = sin(x_i).  coef depends only on params.
// Main kernel: one thread evaluates 2 patches x all 4 wires, wires packed in
// pairs into f32x2 registers (Blackwell packed FFMA2), coefficients streamed
// from shared memory (broadcast LDS.128), nested Horner (tiny live state).
// ---------------------------------------------------------------------------

typedef unsigned long long ull;

#define N_PATCHES (4096 * 196)

// coef interleaved by wire: g_coef4[q*4 + w], q = ((t0*3+t1)*3+t2)*3+t3
__device__ __align__(16) float g_coef4[324];

struct cplx { float re, im; };
__device__ __forceinline__ cplx cmul(cplx a, cplx b) {
    return { a.re * b.re - a.im * b.im, a.re * b.im + a.im * b.re };
}
__device__ __forceinline__ cplx cadd(cplx a, cplx b) {
    return { a.re + b.re, a.im + b.im };
}

// ---------------------------------------------------------------------------
// Setup: one block. Builds the 16x16 circuit unitary column-wise, forms
// A_w = Re(W^H Z_w W), expands into 324 multilinear coefficients.
// ---------------------------------------------------------------------------
__global__ void quanv_setup_kernel(const float* __restrict__ params)
{
    __shared__ float Wr[16][16];
    __shared__ float Wi[16][16];
    __shared__ float A[4][16][16];

    const int tid = threadIdx.x;

    if (tid < 16) {
        cplx s[16];
        #pragma unroll
        for (int m = 0; m < 16; m++) s[m] = { 0.f, 0.f };
        s[tid] = { 1.f, 0.f };

        for (int l = 0; l < 2; l++) {
            for (int w = 0; w < 4; w++) {
                const float a = params[(l * 4 + w) * 3 + 0] * 0.5f;
                const float b = params[(l * 4 + w) * 3 + 1] * 0.5f;
                const float c = params[(l * 4 + w) * 3 + 2] * 0.5f;
                const float ca = cosf(a), sa = sinf(a);
                const float cb = cosf(b), sb = sinf(b);
                const float cc = cosf(c), sc = sinf(c);
                cplx m00 = {  cb * ca, -sb * ca };
                cplx m01 = { -cb * sa,  sb * sa };
                cplx m10 = {  cb * sa,  sb * sa };
                cplx m11 = {  cb * ca,  sb * ca };
                cplx rx00 = { cc, 0.f }, rx01 = { 0.f, -sc };
                cplx rx10 = { 0.f, -sc }, rx11 = { cc, 0.f };
                cplx G00 = cadd(cmul(rx00, m00), cmul(rx01, m10));
                cplx G01 = cadd(cmul(rx00, m01), cmul(rx01, m11));
                cplx G10 = cadd(cmul(rx10, m00), cmul(rx11, m10));
                cplx G11 = cadd(cmul(rx10, m01), cmul(rx11, m11));

                const int mask = 8 >> w;
                #pragma unroll
                for (int m = 0; m < 16; m++) {
                    if (m & mask) continue;
                    cplx s0 = s[m], s1 = s[m | mask];
                    s[m]        = cadd(cmul(G00, s0), cmul(G01, s1));
                    s[m | mask] = cadd(cmul(G10, s0), cmul(G11, s1));
                }
            }
            const int cw[4] = { 0, 1, 2, 3 };
            const int tw[4] = { 1, 2, 3, 0 };
            for (int q = 0; q < 4; q++) {
                const int mc = 8 >> cw[q];
                const int mt = 8 >> tw[q];
                #pragma unroll
                for (int m = 0; m < 16; m++) {
                    if ((m & mc) && !(m & mt)) {
                        cplx tmp = s[m]; s[m] = s[m | mt]; s[m | mt] = tmp;
                    }
                }
            }
        }
        #pragma unroll
        for (int m = 0; m < 16; m++) { Wr[m][tid] = s[m].re; Wi[m][tid] = s[m].im; }
    }
    __syncthreads();

    if (tid < 256) {
        const int j = tid >> 4, k = tid & 15;
        float acc0 = 0.f, acc1 = 0.f, acc2 = 0.f, acc3 = 0.f;
        #pragma unroll
        for (int m = 0; m < 16; m++) {
            const float v = Wr[m][j] * Wr[m][k] + Wi[m][j] * Wi[m][k];
            acc0 += ((m >> 3) & 1) ? -v : v;
            acc1 += ((m >> 2) & 1) ? -v : v;
            acc2 += ((m >> 1) & 1) ? -v : v;
            acc3 += ( m       & 1) ? -v : v;
        }
        A[0][j][k] = acc0; A[1][j][k] = acc1; A[2][j][k] = acc2; A[3][j][k] = acc3;
    }
    __syncthreads();

    if (tid < 324) {
        const int w = tid / 81, q = tid % 81;
        const int t0 = q / 27, t1 = (q / 9) % 3, t2 = (q / 3) % 3, t3 = q % 3;
        const int t[4] = { t0, t1, t2, t3 };
        float c = 0.f;
        for (int j = 0; j < 16; j++) {
            for (int k = 0; k < 16; k++) {
                float h = 1.f;
                #pragma unroll
                for (int i = 0; i < 4; i++) {
                    const int jb = (j >> (3 - i)) & 1;
                    const int kb = (k >> (3 - i)) & 1;
                    const int ti = t[i];
                    float hv;
                    if (ti == 2)       hv = (jb != kb) ? 0.5f : 0.f;   // sin
                    else if (jb != kb) hv = 0.f;
                    else if (ti == 1)  hv = jb ? -0.5f : 0.5f;         // cos
                    else               hv = 0.5f;                      // 1
                    h *= hv;
                }
                c = fmaf(A[w][j][k], h, c);
            }
        }
        g_coef4[q * 4 + w] = c;
    }
}

// ---------------------------------------------------------------------------
// Packed f32x2 helpers (Blackwell sm_100+).
// ---------------------------------------------------------------------------
__device__ __forceinline__ ull ffma2(ull a, ull b, ull c) {
    ull d;
    asm("fma.rn.f32x2 %0, %1, %2, %3;" : "=l"(d) : "l"(a), "l"(b), "l"(c));
    return d;
}
__device__ __forceinline__ ull pack2(float x) {
    ull d;
    asm("mov.b64 %0, {%1, %1};" : "=l"(d) : "f"(x));
    return d;
}
__device__ __forceinline__ ull pack2f(float x, float y) {
    ull d;
    asm("mov.b64 %0, {%1, %2};" : "=l"(d) : "f"(x), "f"(y));
    return d;
}
__device__ __forceinline__ void unpack2(ull v, float& lo, float& hi) {
    asm("mov.b64 {%0, %1}, %2;" : "=f"(lo), "=f"(hi) : "l"(v));
}

// Load the 4 pixels of a patch and produce packed (c,c)/(s,s) duplicates.
struct Trig { ull c0, s0, c1, s1, c2, s2, c3, s3; };

__device__ __forceinline__ Trig load_trig(const float* __restrict__ x, int pidx)
{
    const int b   = pidx / 196;
    const int p   = pidx - b * 196;
    const int r   = p / 14;
    const int col = p - r * 14;
    const float* xp = x + b * 784 + r * 56 + col * 2;
    const float2 top = *(const float2*)xp;
    const float2 bot = *(const float2*)(xp + 28);
    float c0, s0, c1, s1, c2, s2, c3, s3;
    __sincosf(top.x, &s0, &c0);
    __sincosf(top.y, &s1, &c1);
    __sincosf(bot.x, &s2, &c2);
    __sincosf(bot.y, &s3, &c3);
    Trig t;
    t.c0 = pack2(c0); t.s0 = pack2(s0);
    t.c1 = pack2(c1); t.s1 = pack2(s1);
    t.c2 = pack2(c2); t.s2 = pack2(s2);
    t.c3 = pack2(c3); t.s3 = pack2(s3);
    return t;
}

// ---------------------------------------------------------------------------
// Main kernel: 256 threads/block, each thread evaluates 2 patches.
// Shared coef layout: sh[2*q] = packed (w0,w1), sh[2*q+1] = packed (w2,w3).
// Nested streaming Horner: 160 FFMA2 + 81 LDS.128 per 2 patches per thread.
// ---------------------------------------------------------------------------
__global__ void __launch_bounds__(256)
quanv_main_kernel(const float* __restrict__ x, float* __restrict__ out)
{
    __shared__ __align__(16) ull sh[162];
    const int tid = threadIdx.x;

    if (tid < 81) {
        const float4 v = ((const float4*)g_coef4)[tid];
        sh[2 * tid]     = pack2f(v.x, v.y);
        sh[2 * tid + 1] = pack2f(v.z, v.w);
    }
    __syncthreads();

    const int p0 = blockIdx.x * 512 + tid;   // patch for "A"
    const int p1 = p0 + 256;                 // patch for "B"

    const Trig ta = load_trig(x, p0);
    const Trig tb = load_trig(x, p1);

    ull a0x, a0y;   // accumulators, patch A, pairs (w0,w1)/(w2,w3)
    ull b0x, b0y;   // patch B

    #pragma unroll
    for (int t0 = 0; t0 < 3; t0++) {
        ull a1x, a1y, b1x, b1y;
        #pragma unroll
        for (int t1 = 0; t1 < 3; t1++) {
            ull a2x, a2y, b2x, b2y;
            #pragma unroll
            for (int t2 = 0; t2 < 3; t2++) {
                const int q = ((t0 * 3 + t1) * 3 + t2) * 3;
                const ulonglong2 e0 = ((const ulonglong2*)sh)[q];
                const ulonglong2 e1 = ((const ulonglong2*)sh)[q + 1];
                const ulonglong2 e2 = ((const ulonglong2*)sh)[q + 2];

                const ull iax = ffma2(e2.x, ta.s3, ffma2(e1.x, ta.c3, e0.x));
                const ull iay = ffma2(e2.y, ta.s3, ffma2(e1.y, ta.c3, e0.y));
                const ull ibx = ffma2(e2.x, tb.s3, ffma2(e1.x, tb.c3, e0.x));
                const ull iby = ffma2(e2.y, tb.s3, ffma2(e1.y, tb.c3, e0.y));

                if (t2 == 0)      { a2x = iax; a2y = iay; b2x = ibx; b2y = iby; }
                else if (t2 == 1) { a2x = ffma2(iax, ta.c2, a2x); a2y = ffma2(iay, ta.c2, a2y);
                                    b2x = ffma2(ibx, tb.c2, b2x); b2y = ffma2(iby, tb.c2, b2y); }
                else              { a2x = ffma2(iax, ta.s2, a2x); a2y = ffma2(iay, ta.s2, a2y);
                                    b2x = ffma2(ibx, tb.s2, b2x); b2y = ffma2(iby, tb.s2, b2y); }
            }
            if (t1 == 0)      { a1x = a2x; a1y = a2y; b1x = b2x; b1y = b2y; }
            else if (t1 == 1) { a1x = ffma2(a2x, ta.c1, a1x); a1y = ffma2(a2y, ta.c1, a1y);
                                b1x = ffma2(b2x, tb.c1, b1x); b1y = ffma2(b2y, tb.c1, b1y); }
            else              { a1x = ffma2(a2x, ta.s1, a1x); a1y = ffma2(a2y, ta.s1, a1y);
                                b1x = ffma2(b2x, tb.s1, b1x); b1y = ffma2(b2y, tb.s1, b1y); }
        }
        if (t0 == 0)      { a0x = a1x; a0y = a1y; b0x = b1x; b0y = b1y; }
        else if (t0 == 1) { a0x = ffma2(a1x, ta.c0, a0x); a0y = ffma2(a1y, ta.c0, a0y);
                            b0x = ffma2(b1x, tb.c0, b0x); b0y = ffma2(b1y, tb.c0, b0y); }
        else              { a0x = ffma2(a1x, ta.s0, a0x); a0y = ffma2(a1y, ta.s0, a0y);
                            b0x = ffma2(b1x, tb.s0, b0x); b0y = ffma2(b1y, tb.s0, b0y); }
    }

    float4 oa, ob;
    unpack2(a0x, oa.x, oa.y);
    unpack2(a0y, oa.z, oa.w);
    unpack2(b0x, ob.x, ob.y);
    unpack2(b0y, ob.z, ob.w);
    ((float4*)out)[p0] = oa;
    ((float4*)out)[p1] = ob;
}

extern "C" void kernel_launch(void* const* d_in, const int* in_sizes, int n_in,
                              void* d_out, int out_size)
{
    const float* x      = (const float*)d_in[0];
    const float* params = (const float*)d_in[1];
    if (n_in >= 2 && in_sizes[0] == 24) {
        params = (const float*)d_in[0];
        x      = (const float*)d_in[1];
    }
    float* out = (float*)d_out;

    quanv_setup_kernel<<<1, 384>>>(params);
    // 802816 patches / (256 threads * 2 patches) = 1568 blocks exactly
    quanv_main_kernel<<<1568, 256>>>(x, out);
}

// round 5
// speedup vs baseline: 1.9482x; 1.4975x over previous
#include <cuda_runtime.h>

// ---------------------------------------------------------------------------
// Quanvolution filter, algebraically collapsed:
//   <Z_w>(patch) = sum_{t in {I,C,S}^4} coef[w][t] * prod_i f_{t_i}(x_i)
// f_I = 1, f_C = cos(x_i), f_S = sin(x_i).  coef depends only on params.
//
// Setup kernel (1 block, 256 thr): builds 16x16 circuit unitary W with
// amplitude-parallel propagation, A_w = Re(W^H Z_w W), then expands the 324
// coefficients using the closed form: only 16 nonzero (j,k) pairs per coef
// (k = j ^ smask, sign = parity(j & cmask), magnitude 2^-4).
//
// Main kernel: 4 patches/thread, wires packed in f32x2 lanes (FFMA2),
// coefficients streamed from shared via broadcast LDS.128 amortized over the
// 4 patches, nested Horner.
// ---------------------------------------------------------------------------

typedef unsigned long long ull;

#define N_PATCHES (4096 * 196)

// coef interleaved by wire: g_coef4[q*4 + w], q = ((t0*3+t1)*3+t2)*3+t3
__device__ __align__(16) float g_coef4[324];

// ---------------------------------------------------------------------------
// Setup
// ---------------------------------------------------------------------------
__global__ void quanv_setup_kernel(const float* __restrict__ params)
{
    __shared__ float  Gr[8][4];    // [gate][row*2+col]
    __shared__ float  Gi[8][4];
    __shared__ float2 cs[256];     // [j*16 + m]
    __shared__ float  Wr[16][16];  // W[m][j]
    __shared__ float  Wi[16][16];
    __shared__ float  A[4][16][16];

    const int tid = threadIdx.x;

    // --- gate matrices G = RX(p2) RZ(p1) RY(p0), one per thread ---
    if (tid < 8) {
        const float a = params[tid * 3 + 0] * 0.5f;
        const float b = params[tid * 3 + 1] * 0.5f;
        const float c = params[tid * 3 + 2] * 0.5f;
        const float ca = cosf(a), sa = sinf(a);
        const float cb = cosf(b), sb = sinf(b);
        const float cc = cosf(c), sc = sinf(c);
        // M = RZ @ RY
        const float m00r =  cb * ca, m00i = -sb * ca;
        const float m01r = -cb * sa, m01i =  sb * sa;
        const float m10r =  cb * sa, m10i =  sb * sa;
        const float m11r =  cb * ca, m11i =  sb * ca;
        // G = RX @ M,  RX = [[cc, -i sc], [-i sc, cc]]
        Gr[tid][0] = cc * m00r + sc * m10i;  Gi[tid][0] = cc * m00i - sc * m10r;
        Gr[tid][1] = cc * m01r + sc * m11i;  Gi[tid][1] = cc * m01i - sc * m11r;
        Gr[tid][2] = cc * m10r + sc * m00i;  Gi[tid][2] = cc * m10i - sc * m00r;
        Gr[tid][3] = cc * m11r + sc * m01i;  Gi[tid][3] = cc * m11i - sc * m01r;
    }
    __syncthreads();

    // --- amplitude-parallel propagation: thread = (column j, amplitude m) ---
    const int j = tid >> 4;
    const int m = tid & 15;
    float2 s = (m == j) ? make_float2(1.f, 0.f) : make_float2(0.f, 0.f);

    #pragma unroll
    for (int l = 0; l < 2; l++) {
        #pragma unroll
        for (int w = 0; w < 4; w++) {
            cs[tid] = s;
            __syncthreads();
            const int mask = 8 >> w;
            const int b = (m & mask) ? 1 : 0;
            const float2 s0 = cs[(j << 4) | (m & ~mask)];
            const float2 s1 = cs[(j << 4) | (m |  mask)];
            const int g = l * 4 + w;
            const float g0r = Gr[g][b * 2 + 0], g0i = Gi[g][b * 2 + 0];
            const float g1r = Gr[g][b * 2 + 1], g1i = Gi[g][b * 2 + 1];
            float2 ns;
            ns.x = g0r * s0.x - g0i * s0.y + g1r * s1.x - g1i * s1.y;
            ns.y = g0r * s0.y + g0i * s0.x + g1r * s1.y + g1i * s1.x;
            s = ns;
            __syncthreads();
        }
        // CNOT ring (0,1)(1,2)(2,3)(3,0), composed into one permutation.
        // s_out[m] = s_in[f01(f12(f23(f30(m))))], fct(m) = m ^ ((m&maskc)?maskt:0)
        cs[tid] = s;
        __syncthreads();
        int ms = m;
        ms ^= (ms & 1) ? 8 : 0;   // f30: c=wire3(mask1) t=wire0(mask8)
        ms ^= (ms & 2) ? 1 : 0;   // f23
        ms ^= (ms & 4) ? 2 : 0;   // f12
        ms ^= (ms & 8) ? 4 : 0;   // f01
        s = cs[(j << 4) | ms];
        __syncthreads();
    }
    Wr[m][j] = s.x;
    Wi[m][j] = s.y;
    __syncthreads();

    // --- A_w[j][k] = sum_m z_w(m) Re(conj(W[m,j]) W[m,k]) ---
    {
        const int jj = tid >> 4, kk = tid & 15;
        float acc0 = 0.f, acc1 = 0.f, acc2 = 0.f, acc3 = 0.f;
        #pragma unroll
        for (int mm = 0; mm < 16; mm++) {
            const float v = Wr[mm][jj] * Wr[mm][kk] + Wi[mm][jj] * Wi[mm][kk];
            acc0 += ((mm >> 3) & 1) ? -v : v;
            acc1 += ((mm >> 2) & 1) ? -v : v;
            acc2 += ((mm >> 1) & 1) ? -v : v;
            acc3 += ( mm       & 1) ? -v : v;
        }
        A[0][jj][kk] = acc0; A[1][jj][kk] = acc1;
        A[2][jj][kk] = acc2; A[3][jj][kk] = acc3;
    }
    __syncthreads();

    // --- coefficient expansion: 16 signed terms per coefficient ---
    for (int idx = tid; idx < 324; idx += 256) {
        const int q = idx >> 2, w = idx & 3;
        const int t0 = q / 27, t1 = (q / 9) % 3, t2 = (q / 3) % 3, t3 = q % 3;
        int smask = 0, cmask = 0;
        if (t0 == 2) smask |= 8; else if (t0 == 1) cmask |= 8;
        if (t1 == 2) smask |= 4; else if (t1 == 1) cmask |= 4;
        if (t2 == 2) smask |= 2; else if (t2 == 1) cmask |= 2;
        if (t3 == 2) smask |= 1; else if (t3 == 1) cmask |= 1;
        float c = 0.f;
        #pragma unroll
        for (int u = 0; u < 16; u++) {
            const float v = A[w][u][u ^ smask];
            c += (__popc(u & cmask) & 1) ? -v : v;
        }
        g_coef4[idx] = c * 0.0625f;
    }
}

// ---------------------------------------------------------------------------
// Packed f32x2 helpers (Blackwell sm_100+).
// ---------------------------------------------------------------------------
__device__ __forceinline__ ull ffma2(ull a, ull b, ull c) {
    ull d;
    asm("fma.rn.f32x2 %0, %1, %2, %3;" : "=l"(d) : "l"(a), "l"(b), "l"(c));
    return d;
}
__device__ __forceinline__ ull pack2(float x) {
    ull d;
    asm("mov.b64 %0, {%1, %1};" : "=l"(d) : "f"(x));
    return d;
}
__device__ __forceinline__ ull pack2f(float x, float y) {
    ull d;
    asm("mov.b64 %0, {%1, %2};" : "=l"(d) : "f"(x), "f"(y));
    return d;
}
__device__ __forceinline__ void unpack2(ull v, float& lo, float& hi) {
    asm("mov.b64 {%0, %1}, %2;" : "=f"(lo), "=f"(hi) : "l"(v));
}

struct Trig { ull c0, s0, c1, s1, c2, s2, c3, s3; };

__device__ __forceinline__ Trig load_trig(const float* __restrict__ x, int pidx)
{
    const int b   = pidx / 196;
    const int p   = pidx - b * 196;
    const int r   = p / 14;
    const int col = p - r * 14;
    const float* xp = x + b * 784 + r * 56 + col * 2;
    const float2 top = *(const float2*)xp;
    const float2 bot = *(const float2*)(xp + 28);
    float c0, s0, c1, s1, c2, s2, c3, s3;
    __sincosf(top.x, &s0, &c0);
    __sincosf(top.y, &s1, &c1);
    __sincosf(bot.x, &s2, &c2);
    __sincosf(bot.y, &s3, &c3);
    Trig t;
    t.c0 = pack2(c0); t.s0 = pack2(s0);
    t.c1 = pack2(c1); t.s1 = pack2(s1);
    t.c2 = pack2(c2); t.s2 = pack2(s2);
    t.c3 = pack2(c3); t.s3 = pack2(s3);
    return t;
}

// ---------------------------------------------------------------------------
// Main kernel: 128 threads/block, 4 patches/thread.
// sh[2*q] = packed coef (w0,w1), sh[2*q+1] = packed (w2,w3).
// 81 LDS.128 amortized over 4 patches; 160 FFMA2/patch.
// ---------------------------------------------------------------------------
#define P 4

__global__ void __launch_bounds__(128)
quanv_main_kernel(const float* __restrict__ x, float* __restrict__ out)
{
    __shared__ __align__(16) ull sh[162];
    const int tid = threadIdx.x;

    if (tid < 81) {
        const float4 v = ((const float4*)g_coef4)[tid];
        sh[2 * tid]     = pack2f(v.x, v.y);
        sh[2 * tid + 1] = pack2f(v.z, v.w);
    }
    __syncthreads();

    const int base = blockIdx.x * (128 * P) + tid;

    Trig tg[P];
    #pragma unroll
    for (int i = 0; i < P; i++) tg[i] = load_trig(x, base + i * 128);

    ull a0[P][2], a1[P][2], a2[P][2];

    #pragma unroll
    for (int t0 = 0; t0 < 3; t0++) {
        #pragma unroll
        for (int t1 = 0; t1 < 3; t1++) {
            #pragma unroll
            for (int t2 = 0; t2 < 3; t2++) {
                const int q = ((t0 * 3 + t1) * 3 + t2) * 3;
                const ulonglong2 e0 = ((const ulonglong2*)sh)[q];
                const ulonglong2 e1 = ((const ulonglong2*)sh)[q + 1];
                const ulonglong2 e2 = ((const ulonglong2*)sh)[q + 2];

                #pragma unroll
                for (int i = 0; i < P; i++) {
                    const ull ix = ffma2(e2.x, tg[i].s3, ffma2(e1.x, tg[i].c3, e0.x));
                    const ull iy = ffma2(e2.y, tg[i].s3, ffma2(e1.y, tg[i].c3, e0.y));
                    if (t2 == 0)      { a2[i][0] = ix; a2[i][1] = iy; }
                    else if (t2 == 1) { a2[i][0] = ffma2(ix, tg[i].c2, a2[i][0]);
                                        a2[i][1] = ffma2(iy, tg[i].c2, a2[i][1]); }
                    else              { a2[i][0] = ffma2(ix, tg[i].s2, a2[i][0]);
                                        a2[i][1] = ffma2(iy, tg[i].s2, a2[i][1]); }
                }
            }
            #pragma unroll
            for (int i = 0; i < P; i++) {
                if (t1 == 0)      { a1[i][0] = a2[i][0]; a1[i][1] = a2[i][1]; }
                else if (t1 == 1) { a1[i][0] = ffma2(a2[i][0], tg[i].c1, a1[i][0]);
                                    a1[i][1] = ffma2(a2[i][1], tg[i].c1, a1[i][1]); }
                else              { a1[i][0] = ffma2(a2[i][0], tg[i].s1, a1[i][0]);
                                    a1[i][1] = ffma2(a2[i][1], tg[i].s1, a1[i][1]); }
            }
        }
        #pragma unroll
        for (int i = 0; i < P; i++) {
            if (t0 == 0)      { a0[i][0] = a1[i][0]; a0[i][1] = a1[i][1]; }
            else if (t0 == 1) { a0[i][0] = ffma2(a1[i][0], tg[i].c0, a0[i][0]);
                                a0[i][1] = ffma2(a1[i][1], tg[i].c0, a0[i][1]); }
            else              { a0[i][0] = ffma2(a1[i][0], tg[i].s0, a0[i][0]);
                                a0[i][1] = ffma2(a1[i][1], tg[i].s0, a0[i][1]); }
        }
    }

    #pragma unroll
    for (int i = 0; i < P; i++) {
        float4 o;
        unpack2(a0[i][0], o.x, o.y);
        unpack2(a0[i][1], o.z, o.w);
        ((float4*)out)[base + i * 128] = o;
    }
}

extern "C" void kernel_launch(void* const* d_in, const int* in_sizes, int n_in,
                              void* d_out, int out_size)
{
    const float* x      = (const float*)d_in[0];
    const float* params = (const float*)d_in[1];
    if (n_in >= 2 && in_sizes[0] == 24) {
        params = (const float*)d_in[0];
        x      = (const float*)d_in[1];
    }
    float* out = (float*)d_out;

    quanv_setup_kernel<<<1, 256>>>(params);
    // 802816 patches / (128 threads * 4 patches) = 1568 blocks exactly
    quanv_main_kernel<<<1568, 128>>>(x, out);
}